// round 4
// baseline (speedup 1.0000x reference)
#include <cuda_runtime.h>
#include <cuda_bf16.h>
#include <math.h>

// ---------------------------------------------------------------------------
// CrossAttentionFusion: fully fused 3-layer transformer (seq=4) on GB300.
// Strategy: 16 samples (64 token rows) per CTA; residual stream fp32 in SMEM;
// all GEMMs via mma.sync.m16n8k16 bf16 against weights prepacked (per launch)
// into fragment layout in a __device__ scratch buffer (L2-resident).
// ---------------------------------------------------------------------------

#define TS 16          // samples per CTA
#define MROWS 64       // token rows per CTA (= TS*4)
#define DIM 256
#define HB_STRIDE 264  // bf16 elems, padded to dodge bank conflicts
#define QS 776         // qkv smem stride (768 + 8 pad)

#define XS_OFF   0
#define HB_OFF   65536
#define QKV_OFF  99328
#define SMEM_BYTES 198656

// Packed weights: per layer 98304 uint2 (qkv 49152, Wo 16384, W1 16384, W2 16384)
__device__ uint2 g_packed[3 * 98304];

// Pack fp32 weight matrix [K=256, N] (row-major) into mma B-fragment order.
// Fragment (m16n8k16, .row.col): thread t holds b0={B[k0][n],B[k0+1][n]},
// b1={B[k0+8][n],B[k0+9][n]} with k0=kt*16+(t%4)*2, n=nt*8+(t/4).
// Linear index: (nt*16 + kt)*32 + t.
__global__ void pack_w(const float* __restrict__ src, int dstOff, int N) {
    int id = blockIdx.x * 256 + threadIdx.x;
    int total = (N >> 3) * 512;
    if (id >= total) return;
    int lane = id & 31;
    int kt = (id >> 5) & 15;
    int nt = id >> 9;
    int g = lane >> 2, tg = lane & 3;
    int k0 = kt * 16 + tg * 2, n = nt * 8 + g;
    unsigned lo0 = __bfloat16_as_ushort(__float2bfloat16(src[(size_t)k0 * N + n]));
    unsigned hi0 = __bfloat16_as_ushort(__float2bfloat16(src[(size_t)(k0 + 1) * N + n]));
    unsigned lo1 = __bfloat16_as_ushort(__float2bfloat16(src[(size_t)(k0 + 8) * N + n]));
    unsigned hi1 = __bfloat16_as_ushort(__float2bfloat16(src[(size_t)(k0 + 9) * N + n]));
    g_packed[dstOff + id] = make_uint2(lo0 | (hi0 << 16), lo1 | (hi1 << 16));
}

__device__ __forceinline__ float gelu_exact(float v) {
    return 0.5f * v * (1.0f + erff(v * 0.70710678118654752f));
}

__device__ __forceinline__ float2 warp_red2(float s, float s2) {
    #pragma unroll
    for (int o = 16; o; o >>= 1) {
        s  += __shfl_xor_sync(0xffffffffu, s, o);
        s2 += __shfl_xor_sync(0xffffffffu, s2, o);
    }
    return make_float2(s, s2);
}

// C[64, N] = A[64, 256]_bf16smem @ Wpacked + bias, with epilogue:
// MODE 0: store bf16 to out (stride ostride)
// MODE 1: store bf16 gelu(.) to out
// MODE 2: xs[64,256] += .
template <int MODE>
__device__ __forceinline__ void gemm64(const __nv_bfloat16* __restrict__ A, int lda,
                                       const uint2* __restrict__ W, int N,
                                       const float* __restrict__ bias,
                                       __nv_bfloat16* __restrict__ out, int ostride,
                                       float* __restrict__ xs) {
    const int lane = threadIdx.x & 31, warp = threadIdx.x >> 5;
    const int wm = warp & 3, wn = warp >> 2;
    const int g = lane >> 2, tg = lane & 3;
    const int r0 = wm * 16 + g, r1 = r0 + 8;
    const int nchunks = N >> 7;
    for (int ch = 0; ch < nchunks; ch++) {
        float acc[8][4];
        #pragma unroll
        for (int i = 0; i < 8; i++) { acc[i][0] = acc[i][1] = acc[i][2] = acc[i][3] = 0.f; }
        const int ntbase = ch * 16 + wn * 8;
        #pragma unroll 4
        for (int kt = 0; kt < 16; kt++) {
            const int c0 = kt * 16 + tg * 2;
            unsigned a0 = *(const unsigned*)(A + r0 * lda + c0);
            unsigned a1 = *(const unsigned*)(A + r1 * lda + c0);
            unsigned a2 = *(const unsigned*)(A + r0 * lda + c0 + 8);
            unsigned a3 = *(const unsigned*)(A + r1 * lda + c0 + 8);
            const uint2* wp = W + ((size_t)ntbase * 16 + kt) * 32 + lane;
            #pragma unroll
            for (int nt = 0; nt < 8; nt++) {
                uint2 b = wp[nt * 512];
                asm volatile(
                    "mma.sync.aligned.m16n8k16.row.col.f32.bf16.bf16.f32 "
                    "{%0,%1,%2,%3}, {%4,%5,%6,%7}, {%8,%9}, {%0,%1,%2,%3};\n"
                    : "+f"(acc[nt][0]), "+f"(acc[nt][1]), "+f"(acc[nt][2]), "+f"(acc[nt][3])
                    : "r"(a0), "r"(a1), "r"(a2), "r"(a3), "r"(b.x), "r"(b.y));
            }
        }
        #pragma unroll
        for (int nt = 0; nt < 8; nt++) {
            const int cc = (ntbase + nt) * 8 + tg * 2;
            float bb0 = bias[cc], bb1 = bias[cc + 1];
            float v00 = acc[nt][0] + bb0, v01 = acc[nt][1] + bb1;
            float v10 = acc[nt][2] + bb0, v11 = acc[nt][3] + bb1;
            if (MODE == 2) {
                xs[r0 * DIM + cc]     += v00;
                xs[r0 * DIM + cc + 1] += v01;
                xs[r1 * DIM + cc]     += v10;
                xs[r1 * DIM + cc + 1] += v11;
            } else {
                if (MODE == 1) {
                    v00 = gelu_exact(v00); v01 = gelu_exact(v01);
                    v10 = gelu_exact(v10); v11 = gelu_exact(v11);
                }
                *(__nv_bfloat162*)(out + r0 * ostride + cc) = __floats2bfloat162_rn(v00, v01);
                *(__nv_bfloat162*)(out + r1 * ostride + cc) = __floats2bfloat162_rn(v10, v11);
            }
        }
    }
}

// LN all 64 rows of xs -> bf16 dst (gamma/beta per col)
__device__ __forceinline__ void ln64_bf16(const float* __restrict__ xs,
                                          const float* __restrict__ gm,
                                          const float* __restrict__ bt,
                                          __nv_bfloat16* __restrict__ dst, int ds) {
    const int lane = threadIdx.x & 31, warp = threadIdx.x >> 5;
    for (int r = warp; r < MROWS; r += 8) {
        const float* row = xs + r * DIM;
        float v[8], s = 0.f, s2 = 0.f;
        #pragma unroll
        for (int i = 0; i < 8; i++) { v[i] = row[lane + i * 32]; s += v[i]; s2 += v[i] * v[i]; }
        float2 rd = warp_red2(s, s2);
        float m = rd.x * (1.f / DIM);
        float var = rd.y * (1.f / DIM) - m * m;
        float rs = rsqrtf(var + 1e-5f);
        #pragma unroll
        for (int i = 0; i < 8; i++) {
            int c = lane + i * 32;
            dst[r * ds + c] = __float2bfloat16((v[i] - m) * rs * gm[c] + bt[c]);
        }
    }
}

__global__ void __launch_bounds__(256, 1) fused_kernel(
    const float* __restrict__ ge, const float* __restrict__ pe,
    const float* __restrict__ sfeat, const float* __restrict__ ppi,
    const float* __restrict__ symW, const float* __restrict__ symb,
    const float* __restrict__ symg, const float* __restrict__ symbeta,
    const float* __restrict__ tte,
    const float* __restrict__ bqkv, const float* __restrict__ bo,
    const float* __restrict__ ln1g, const float* __restrict__ ln1b,
    const float* __restrict__ ln2g, const float* __restrict__ ln2b,
    const float* __restrict__ b1, const float* __restrict__ b2,
    const float* __restrict__ flng, const float* __restrict__ flnb,
    const float* __restrict__ olng, const float* __restrict__ olnb,
    float* __restrict__ out) {
    extern __shared__ char smem[];
    float* xs = (float*)(smem + XS_OFF);                       // [64][256] fp32 residual
    __nv_bfloat16* hb = (__nv_bfloat16*)(smem + HB_OFF);       // [64][264] bf16 scratch A
    __nv_bfloat16* qkvb = (__nv_bfloat16*)(smem + QKV_OFF);    // [64][776] bf16 qkv / ff1
    const int tid = threadIdx.x;
    const int lane = tid & 31, warp = tid >> 5;
    const int s0 = blockIdx.x * TS;

    // ---------------- Phase 0: build x = stack(tokens) + tte -------------
    float* sfs = (float*)(smem + QKV_OFF);  // [16][64] sym_feat staging
    for (int idx = tid; idx < TS * 64; idx += 256) {
        int s = idx >> 6, j = idx & 63;
        sfs[idx] = sfeat[(size_t)(s0 + s) * 64 + j];
    }
    for (int idx = tid; idx < TS * DIM; idx += 256) {
        int s = idx >> 8, c = idx & 255;
        size_t gsrc = (size_t)(s0 + s) * DIM + c;
        xs[(s * 4 + 0) * DIM + c] = ge[gsrc];
        xs[(s * 4 + 1) * DIM + c] = pe[gsrc];
        xs[(s * 4 + 3) * DIM + c] = ppi[gsrc];
    }
    __syncthreads();
    {   // sym projection: thread = output column
        int c = tid;
        float acc[TS];
        #pragma unroll
        for (int s = 0; s < TS; s++) acc[s] = 0.f;
        for (int j = 0; j < 64; j++) {
            float w = symW[(size_t)j * DIM + c];
            #pragma unroll
            for (int s = 0; s < TS; s++) acc[s] += sfs[s * 64 + j] * w;
        }
        float bb = symb[c];
        #pragma unroll
        for (int s = 0; s < TS; s++) xs[(s * 4 + 2) * DIM + c] = acc[s] + bb;
    }
    __syncthreads();
    // sym LN in place on rows 4s+2
    for (int s = warp; s < TS; s += 8) {
        float* row = xs + (s * 4 + 2) * DIM;
        float v[8], su = 0.f, su2 = 0.f;
        #pragma unroll
        for (int i = 0; i < 8; i++) { v[i] = row[lane + i * 32]; su += v[i]; su2 += v[i] * v[i]; }
        float2 rd = warp_red2(su, su2);
        float m = rd.x * (1.f / DIM), var = rd.y * (1.f / DIM) - m * m;
        float rs = rsqrtf(var + 1e-5f);
        #pragma unroll
        for (int i = 0; i < 8; i++) {
            int c = lane + i * 32;
            row[c] = (v[i] - m) * rs * symg[c] + symbeta[c];
        }
    }
    __syncthreads();
    for (int idx = tid; idx < MROWS * DIM; idx += 256) {
        int r = idx >> 8, c = idx & 255;
        xs[idx] += tte[(r & 3) * DIM + c];
    }
    __syncthreads();

    // ---------------- 3 transformer layers --------------------------------
    for (int l = 0; l < 3; l++) {
        const uint2* pw = g_packed + (size_t)l * 98304;
        ln64_bf16(xs, ln1g + l * DIM, ln1b + l * DIM, hb, HB_STRIDE);
        __syncthreads();
        gemm64<0>(hb, HB_STRIDE, pw, 768, bqkv + l * 768, qkvb, QS, xs);
        __syncthreads();
        // attention: thread = (sample, head); writes o into hb
        if (tid < 128) {
            const int s = tid >> 3, h = tid & 7;
            const __nv_bfloat16* qb = qkvb + (s * 4) * QS + h * 32;
            const __nv_bfloat16* kb = qb + 256;
            const __nv_bfloat16* vb = qb + 512;
            float S[4][4];
            #pragma unroll
            for (int i = 0; i < 4; i++)
                #pragma unroll
                for (int j = 0; j < 4; j++) S[i][j] = 0.f;
            for (int d2 = 0; d2 < 16; d2++) {
                float2 qv[4], kv[4];
                #pragma unroll
                for (int i = 0; i < 4; i++) {
                    qv[i] = __bfloat1622float2(*(const __nv_bfloat162*)(qb + i * QS + d2 * 2));
                    kv[i] = __bfloat1622float2(*(const __nv_bfloat162*)(kb + i * QS + d2 * 2));
                }
                #pragma unroll
                for (int i = 0; i < 4; i++)
                    #pragma unroll
                    for (int j = 0; j < 4; j++)
                        S[i][j] += qv[i].x * kv[j].x + qv[i].y * kv[j].y;
            }
            const float scale = 0.17677669529663687f;  // 1/sqrt(32)
            #pragma unroll
            for (int i = 0; i < 4; i++) {
                float mx = -1e30f;
                #pragma unroll
                for (int j = 0; j < 4; j++) { S[i][j] *= scale; mx = fmaxf(mx, S[i][j]); }
                float sm = 0.f;
                #pragma unroll
                for (int j = 0; j < 4; j++) { S[i][j] = expf(S[i][j] - mx); sm += S[i][j]; }
                float inv = 1.f / sm;
                #pragma unroll
                for (int j = 0; j < 4; j++) S[i][j] *= inv;
            }
            for (int d2 = 0; d2 < 16; d2++) {
                float2 vv[4];
                #pragma unroll
                for (int j = 0; j < 4; j++)
                    vv[j] = __bfloat1622float2(*(const __nv_bfloat162*)(vb + j * QS + d2 * 2));
                #pragma unroll
                for (int i = 0; i < 4; i++) {
                    float ox = 0.f, oy = 0.f;
                    #pragma unroll
                    for (int j = 0; j < 4; j++) { ox += S[i][j] * vv[j].x; oy += S[i][j] * vv[j].y; }
                    *(__nv_bfloat162*)(hb + (s * 4 + i) * HB_STRIDE + h * 32 + d2 * 2) =
                        __floats2bfloat162_rn(ox, oy);
                }
            }
        }
        __syncthreads();
        gemm64<2>(hb, HB_STRIDE, pw + 49152, 256, bo + l * DIM, nullptr, 0, xs);   // x += o @ Wo
        __syncthreads();
        ln64_bf16(xs, ln2g + l * DIM, ln2b + l * DIM, hb, HB_STRIDE);
        __syncthreads();
        gemm64<1>(hb, HB_STRIDE, pw + 65536, 256, b1 + l * DIM, qkvb, QS, xs);     // ff1 = gelu
        __syncthreads();
        gemm64<2>(qkvb, QS, pw + 81920, 256, b2 + l * DIM, nullptr, 0, xs);        // x += ff2
        __syncthreads();
    }

    // ---------------- final LN (in place, fp32) ----------------------------
    for (int r = warp; r < MROWS; r += 8) {
        float* row = xs + r * DIM;
        float v[8], su = 0.f, su2 = 0.f;
        #pragma unroll
        for (int i = 0; i < 8; i++) { v[i] = row[lane + i * 32]; su += v[i]; su2 += v[i] * v[i]; }
        float2 rd = warp_red2(su, su2);
        float m = rd.x * (1.f / DIM), var = rd.y * (1.f / DIM) - m * m;
        float rs = rsqrtf(var + 1e-5f);
        #pragma unroll
        for (int i = 0; i < 8; i++) {
            int c = lane + i * 32;
            row[c] = (v[i] - m) * rs * flng[c] + flnb[c];
        }
    }
    __syncthreads();
    // mean over 4 tokens
    float* ms = (float*)(smem + QKV_OFF);  // [16][256] fp32
    for (int idx = tid; idx < TS * DIM; idx += 256) {
        int s = idx >> 8, c = idx & 255;
        const float* bp = xs + (s * 4) * DIM + c;
        ms[idx] = 0.25f * (bp[0] + bp[DIM] + bp[2 * DIM] + bp[3 * DIM]);
    }
    __syncthreads();
    // out LN -> global
    for (int r = warp; r < TS; r += 8) {
        const float* row = ms + r * DIM;
        float v[8], su = 0.f, su2 = 0.f;
        #pragma unroll
        for (int i = 0; i < 8; i++) { v[i] = row[lane + i * 32]; su += v[i]; su2 += v[i] * v[i]; }
        float2 rd = warp_red2(su, su2);
        float m = rd.x * (1.f / DIM), var = rd.y * (1.f / DIM) - m * m;
        float rs = rsqrtf(var + 1e-5f);
        #pragma unroll
        for (int i = 0; i < 8; i++) {
            int c = lane + i * 32;
            out[(size_t)(s0 + r) * DIM + c] = (v[i] - m) * rs * olng[c] + olnb[c];
        }
    }
}

extern "C" void kernel_launch(void* const* d_in, const int* in_sizes, int n_in,
                              void* d_out, int out_size) {
    const float* ge      = (const float*)d_in[0];
    const float* pe      = (const float*)d_in[1];
    const float* sfeat   = (const float*)d_in[2];
    const float* ppi     = (const float*)d_in[3];
    const float* symW    = (const float*)d_in[4];
    const float* symb    = (const float*)d_in[5];
    const float* symg    = (const float*)d_in[6];
    const float* symbeta = (const float*)d_in[7];
    const float* tte     = (const float*)d_in[8];
    const float* Wqkv    = (const float*)d_in[9];
    const float* bqkv    = (const float*)d_in[10];
    const float* Wo      = (const float*)d_in[11];
    const float* bo      = (const float*)d_in[12];
    const float* ln1g    = (const float*)d_in[13];
    const float* ln1b    = (const float*)d_in[14];
    const float* ln2g    = (const float*)d_in[15];
    const float* ln2b    = (const float*)d_in[16];
    const float* W1      = (const float*)d_in[17];
    const float* b1      = (const float*)d_in[18];
    const float* W2      = (const float*)d_in[19];
    const float* b2      = (const float*)d_in[20];
    const float* flng    = (const float*)d_in[21];
    const float* flnb    = (const float*)d_in[22];
    const float* olng    = (const float*)d_in[23];
    const float* olnb    = (const float*)d_in[24];

    int B = in_sizes[0] / DIM;

    cudaFuncSetAttribute(fused_kernel, cudaFuncAttributeMaxDynamicSharedMemorySize, SMEM_BYTES);

    for (int l = 0; l < 3; l++) {
        pack_w<<<192, 256>>>(Wqkv + (size_t)l * 256 * 768, l * 98304, 768);
        pack_w<<<64, 256>>>(Wo + (size_t)l * 256 * 256, l * 98304 + 49152, 256);
        pack_w<<<64, 256>>>(W1 + (size_t)l * 256 * 256, l * 98304 + 65536, 256);
        pack_w<<<64, 256>>>(W2 + (size_t)l * 256 * 256, l * 98304 + 81920, 256);
    }

    fused_kernel<<<B / TS, 256, SMEM_BYTES>>>(
        ge, pe, sfeat, ppi, symW, symb, symg, symbeta, tte,
        bqkv, bo, ln1g, ln1b, ln2g, ln2b, b1, b2,
        flng, flnb, olng, olnb, (float*)d_out);
}

// round 6
// speedup vs baseline: 1.1542x; 1.1542x over previous
#include <cuda_runtime.h>
#include <cuda_bf16.h>
#include <math.h>

// ---------------------------------------------------------------------------
// CrossAttentionFusion: fully fused 3-layer transformer (seq=4) on GB300.
// R4: de-duplicated weight fetch (each warp owns a disjoint n-slice and walks
// all m-tiles), ldmatrix.x4 A-fragment loads, single weight-pack kernel.
// ---------------------------------------------------------------------------

#define TS 16          // samples per CTA
#define MROWS 64       // token rows per CTA (= TS*4)
#define DIM 256
#define HB_STRIDE 264  // bf16 elems, padded (528B rows: conflict-free ldmatrix)
#define QS 776         // qkv smem stride (768 + 8 pad) -> 1552B rows

#define XS_OFF   0
#define HB_OFF   65536
#define QKV_OFF  99328
#define SMEM_BYTES 198656

// Packed weights: per layer 98304 uint2 (qkv 49152, Wo 16384, W1 16384, W2 16384)
__device__ uint2 g_packed[3 * 98304];

// ---------------------------------------------------------------------------
// Pack ALL fp32 weights into mma B-fragment order in ONE launch.
// Fragment (m16n8k16, .row.col): thread t holds b0={B[k0][n],B[k0+1][n]},
// b1={B[k0+8][n],B[k0+9][n]} with k0=kt*16+(t%4)*2, n=nt*8+(t/4).
// Linear index within a matrix: (nt*16 + kt)*32 + t.
// ---------------------------------------------------------------------------
__global__ void pack_all(const float* __restrict__ Wqkv, const float* __restrict__ Wo,
                         const float* __restrict__ W1, const float* __restrict__ W2) {
    int id = blockIdx.x * 256 + threadIdx.x;        // 0 .. 294911
    int l = id / 98304;
    int r = id - l * 98304;
    const float* src;
    int N, idx;
    if (r < 49152)      { src = Wqkv + (size_t)l * 256 * 768; N = 768; idx = r; }
    else if (r < 65536) { src = Wo + (size_t)l * 65536; N = 256; idx = r - 49152; }
    else if (r < 81920) { src = W1 + (size_t)l * 65536; N = 256; idx = r - 65536; }
    else                { src = W2 + (size_t)l * 65536; N = 256; idx = r - 81920; }
    int lane = idx & 31;
    int kt = (idx >> 5) & 15;
    int nt = idx >> 9;
    int g = lane >> 2, tg = lane & 3;
    int k0 = kt * 16 + tg * 2, n = nt * 8 + g;
    unsigned lo0 = __bfloat16_as_ushort(__float2bfloat16(src[(size_t)k0 * N + n]));
    unsigned hi0 = __bfloat16_as_ushort(__float2bfloat16(src[(size_t)(k0 + 1) * N + n]));
    unsigned lo1 = __bfloat16_as_ushort(__float2bfloat16(src[(size_t)(k0 + 8) * N + n]));
    unsigned hi1 = __bfloat16_as_ushort(__float2bfloat16(src[(size_t)(k0 + 9) * N + n]));
    g_packed[id] = make_uint2(lo0 | (hi0 << 16), lo1 | (hi1 << 16));
}

__device__ __forceinline__ float gelu_exact(float v) {
    return 0.5f * v * (1.0f + erff(v * 0.70710678118654752f));
}

__device__ __forceinline__ float2 warp_red2(float s, float s2) {
    #pragma unroll
    for (int o = 16; o; o >>= 1) {
        s  += __shfl_xor_sync(0xffffffffu, s, o);
        s2 += __shfl_xor_sync(0xffffffffu, s2, o);
    }
    return make_float2(s, s2);
}

// ---------------------------------------------------------------------------
// C[64, N] = A[64, 256]_bf16smem @ Wpacked + bias.
// Warp layout: each warp owns 2 n-tiles per 128-col chunk (disjoint across
// warps -> every weight fragment is fetched from L2 exactly once per CTA)
// and iterates over all 4 m-tiles, loading A via ldmatrix.x4.
// MODE 0: store bf16 to out; MODE 1: store bf16 gelu(.); MODE 2: xs += .
// ---------------------------------------------------------------------------
template <int MODE>
__device__ __forceinline__ void gemm64(const __nv_bfloat16* __restrict__ A, int lda,
                                       const uint2* __restrict__ W, int N,
                                       const float* __restrict__ bias,
                                       __nv_bfloat16* __restrict__ out, int ostride,
                                       float* __restrict__ xs) {
    const int lane = threadIdx.x & 31, warp = threadIdx.x >> 5;
    const int g = lane >> 2, tg = lane & 3;
    const int arow = lane & 15;            // ldmatrix row within m-tile
    const int acol = (lane >> 4) << 3;     // ldmatrix col half-select
    unsigned sbase = (unsigned)__cvta_generic_to_shared(A);
    unsigned amt[4];
    #pragma unroll
    for (int mt = 0; mt < 4; mt++)
        amt[mt] = sbase + (unsigned)(((mt * 16 + arow) * lda + acol) * 2);

    const int nchunks = N >> 7;
    for (int ch = 0; ch < nchunks; ch++) {
        const int nt0 = ch * 16 + warp * 2;
        float acc[4][2][4];
        #pragma unroll
        for (int mt = 0; mt < 4; mt++)
            #pragma unroll
            for (int j = 0; j < 2; j++)
                acc[mt][j][0] = acc[mt][j][1] = acc[mt][j][2] = acc[mt][j][3] = 0.f;

        const uint2* wp0 = W + (size_t)nt0 * 512 + lane;  // (nt0*16)*32 + lane
        #pragma unroll
        for (int kt = 0; kt < 16; kt++) {
            uint2 b0 = wp0[kt * 32];
            uint2 b1 = wp0[kt * 32 + 512];
            #pragma unroll
            for (int mt = 0; mt < 4; mt++) {
                unsigned a0, a1, a2, a3;
                unsigned aaddr = amt[mt] + (unsigned)(kt * 32);
                asm volatile(
                    "ldmatrix.sync.aligned.m8n8.x4.shared.b16 {%0,%1,%2,%3}, [%4];\n"
                    : "=r"(a0), "=r"(a1), "=r"(a2), "=r"(a3) : "r"(aaddr));
                asm volatile(
                    "mma.sync.aligned.m16n8k16.row.col.f32.bf16.bf16.f32 "
                    "{%0,%1,%2,%3}, {%4,%5,%6,%7}, {%8,%9}, {%0,%1,%2,%3};\n"
                    : "+f"(acc[mt][0][0]), "+f"(acc[mt][0][1]),
                      "+f"(acc[mt][0][2]), "+f"(acc[mt][0][3])
                    : "r"(a0), "r"(a1), "r"(a2), "r"(a3), "r"(b0.x), "r"(b0.y));
                asm volatile(
                    "mma.sync.aligned.m16n8k16.row.col.f32.bf16.bf16.f32 "
                    "{%0,%1,%2,%3}, {%4,%5,%6,%7}, {%8,%9}, {%0,%1,%2,%3};\n"
                    : "+f"(acc[mt][1][0]), "+f"(acc[mt][1][1]),
                      "+f"(acc[mt][1][2]), "+f"(acc[mt][1][3])
                    : "r"(a0), "r"(a1), "r"(a2), "r"(a3), "r"(b1.x), "r"(b1.y));
            }
        }
        // epilogue
        #pragma unroll
        for (int j = 0; j < 2; j++) {
            const int cc = (nt0 + j) * 8 + tg * 2;
            const float bb0 = bias[cc], bb1 = bias[cc + 1];
            #pragma unroll
            for (int mt = 0; mt < 4; mt++) {
                const int r0 = mt * 16 + g, r1 = r0 + 8;
                float v00 = acc[mt][j][0] + bb0, v01 = acc[mt][j][1] + bb1;
                float v10 = acc[mt][j][2] + bb0, v11 = acc[mt][j][3] + bb1;
                if (MODE == 2) {
                    xs[r0 * DIM + cc]     += v00;
                    xs[r0 * DIM + cc + 1] += v01;
                    xs[r1 * DIM + cc]     += v10;
                    xs[r1 * DIM + cc + 1] += v11;
                } else {
                    if (MODE == 1) {
                        v00 = gelu_exact(v00); v01 = gelu_exact(v01);
                        v10 = gelu_exact(v10); v11 = gelu_exact(v11);
                    }
                    *(__nv_bfloat162*)(out + r0 * ostride + cc) = __floats2bfloat162_rn(v00, v01);
                    *(__nv_bfloat162*)(out + r1 * ostride + cc) = __floats2bfloat162_rn(v10, v11);
                }
            }
        }
    }
}

// LN all 64 rows of xs -> bf16 dst (gamma/beta per col)
__device__ __forceinline__ void ln64_bf16(const float* __restrict__ xs,
                                          const float* __restrict__ gm,
                                          const float* __restrict__ bt,
                                          __nv_bfloat16* __restrict__ dst, int ds) {
    const int lane = threadIdx.x & 31, warp = threadIdx.x >> 5;
    for (int r = warp; r < MROWS; r += 8) {
        const float* row = xs + r * DIM;
        float v[8], s = 0.f, s2 = 0.f;
        #pragma unroll
        for (int i = 0; i < 8; i++) { v[i] = row[lane + i * 32]; s += v[i]; s2 += v[i] * v[i]; }
        float2 rd = warp_red2(s, s2);
        float m = rd.x * (1.f / DIM);
        float var = rd.y * (1.f / DIM) - m * m;
        float rs = rsqrtf(var + 1e-5f);
        #pragma unroll
        for (int i = 0; i < 8; i++) {
            int c = lane + i * 32;
            dst[r * ds + c] = __float2bfloat16((v[i] - m) * rs * gm[c] + bt[c]);
        }
    }
}

__global__ void __launch_bounds__(256, 1) fused_kernel(
    const float* __restrict__ ge, const float* __restrict__ pe,
    const float* __restrict__ sfeat, const float* __restrict__ ppi,
    const float* __restrict__ symW, const float* __restrict__ symb,
    const float* __restrict__ symg, const float* __restrict__ symbeta,
    const float* __restrict__ tte,
    const float* __restrict__ bqkv, const float* __restrict__ bo,
    const float* __restrict__ ln1g, const float* __restrict__ ln1b,
    const float* __restrict__ ln2g, const float* __restrict__ ln2b,
    const float* __restrict__ b1, const float* __restrict__ b2,
    const float* __restrict__ flng, const float* __restrict__ flnb,
    const float* __restrict__ olng, const float* __restrict__ olnb,
    float* __restrict__ out) {
    extern __shared__ char smem[];
    float* xs = (float*)(smem + XS_OFF);                       // [64][256] fp32 residual
    __nv_bfloat16* hb = (__nv_bfloat16*)(smem + HB_OFF);       // [64][264] bf16 scratch A
    __nv_bfloat16* qkvb = (__nv_bfloat16*)(smem + QKV_OFF);    // [64][776] bf16 qkv / ff1
    const int tid = threadIdx.x;
    const int lane = tid & 31, warp = tid >> 5;
    const int s0 = blockIdx.x * TS;

    // ---------------- Phase 0: build x = stack(tokens) + tte -------------
    float* sfs = (float*)(smem + QKV_OFF);  // [16][64] sym_feat staging
    for (int idx = tid; idx < TS * 64; idx += 256) {
        int s = idx >> 6, j = idx & 63;
        sfs[idx] = sfeat[(size_t)(s0 + s) * 64 + j];
    }
    for (int idx = tid; idx < TS * DIM; idx += 256) {
        int s = idx >> 8, c = idx & 255;
        size_t gsrc = (size_t)(s0 + s) * DIM + c;
        xs[(s * 4 + 0) * DIM + c] = ge[gsrc];
        xs[(s * 4 + 1) * DIM + c] = pe[gsrc];
        xs[(s * 4 + 3) * DIM + c] = ppi[gsrc];
    }
    __syncthreads();
    {   // sym projection: thread = output column
        int c = tid;
        float acc[TS];
        #pragma unroll
        for (int s = 0; s < TS; s++) acc[s] = 0.f;
        for (int j = 0; j < 64; j++) {
            float w = symW[(size_t)j * DIM + c];
            #pragma unroll
            for (int s = 0; s < TS; s++) acc[s] += sfs[s * 64 + j] * w;
        }
        float bb = symb[c];
        #pragma unroll
        for (int s = 0; s < TS; s++) xs[(s * 4 + 2) * DIM + c] = acc[s] + bb;
    }
    __syncthreads();
    // sym LN in place on rows 4s+2
    for (int s = warp; s < TS; s += 8) {
        float* row = xs + (s * 4 + 2) * DIM;
        float v[8], su = 0.f, su2 = 0.f;
        #pragma unroll
        for (int i = 0; i < 8; i++) { v[i] = row[lane + i * 32]; su += v[i]; su2 += v[i] * v[i]; }
        float2 rd = warp_red2(su, su2);
        float m = rd.x * (1.f / DIM), var = rd.y * (1.f / DIM) - m * m;
        float rs = rsqrtf(var + 1e-5f);
        #pragma unroll
        for (int i = 0; i < 8; i++) {
            int c = lane + i * 32;
            row[c] = (v[i] - m) * rs * symg[c] + symbeta[c];
        }
    }
    __syncthreads();
    for (int idx = tid; idx < MROWS * DIM; idx += 256) {
        int r = idx >> 8, c = idx & 255;
        xs[idx] += tte[(r & 3) * DIM + c];
    }
    __syncthreads();

    // ---------------- 3 transformer layers --------------------------------
    for (int l = 0; l < 3; l++) {
        const uint2* pw = g_packed + (size_t)l * 98304;
        ln64_bf16(xs, ln1g + l * DIM, ln1b + l * DIM, hb, HB_STRIDE);
        __syncthreads();
        gemm64<0>(hb, HB_STRIDE, pw, 768, bqkv + l * 768, qkvb, QS, xs);
        __syncthreads();
        // attention: thread = (sample, head); writes o into hb
        if (tid < 128) {
            const int s = tid >> 3, h = tid & 7;
            const __nv_bfloat16* qb = qkvb + (s * 4) * QS + h * 32;
            const __nv_bfloat16* kb = qb + 256;
            const __nv_bfloat16* vb = qb + 512;
            float S[4][4];
            #pragma unroll
            for (int i = 0; i < 4; i++)
                #pragma unroll
                for (int j = 0; j < 4; j++) S[i][j] = 0.f;
            for (int d2 = 0; d2 < 16; d2++) {
                float2 qv[4], kv[4];
                #pragma unroll
                for (int i = 0; i < 4; i++) {
                    qv[i] = __bfloat1622float2(*(const __nv_bfloat162*)(qb + i * QS + d2 * 2));
                    kv[i] = __bfloat1622float2(*(const __nv_bfloat162*)(kb + i * QS + d2 * 2));
                }
                #pragma unroll
                for (int i = 0; i < 4; i++)
                    #pragma unroll
                    for (int j = 0; j < 4; j++)
                        S[i][j] += qv[i].x * kv[j].x + qv[i].y * kv[j].y;
            }
            const float scale = 0.17677669529663687f;  // 1/sqrt(32)
            #pragma unroll
            for (int i = 0; i < 4; i++) {
                float mx = -1e30f;
                #pragma unroll
                for (int j = 0; j < 4; j++) { S[i][j] *= scale; mx = fmaxf(mx, S[i][j]); }
                float sm = 0.f;
                #pragma unroll
                for (int j = 0; j < 4; j++) { S[i][j] = expf(S[i][j] - mx); sm += S[i][j]; }
                float inv = 1.f / sm;
                #pragma unroll
                for (int j = 0; j < 4; j++) S[i][j] *= inv;
            }
            for (int d2 = 0; d2 < 16; d2++) {
                float2 vv[4];
                #pragma unroll
                for (int j = 0; j < 4; j++)
                    vv[j] = __bfloat1622float2(*(const __nv_bfloat162*)(vb + j * QS + d2 * 2));
                #pragma unroll
                for (int i = 0; i < 4; i++) {
                    float ox = 0.f, oy = 0.f;
                    #pragma unroll
                    for (int j = 0; j < 4; j++) { ox += S[i][j] * vv[j].x; oy += S[i][j] * vv[j].y; }
                    *(__nv_bfloat162*)(hb + (s * 4 + i) * HB_STRIDE + h * 32 + d2 * 2) =
                        __floats2bfloat162_rn(ox, oy);
                }
            }
        }
        __syncthreads();
        gemm64<2>(hb, HB_STRIDE, pw + 49152, 256, bo + l * DIM, nullptr, 0, xs);   // x += o @ Wo
        __syncthreads();
        ln64_bf16(xs, ln2g + l * DIM, ln2b + l * DIM, hb, HB_STRIDE);
        __syncthreads();
        gemm64<1>(hb, HB_STRIDE, pw + 65536, 256, b1 + l * DIM, qkvb, QS, xs);     // ff1 = gelu
        __syncthreads();
        gemm64<2>(qkvb, QS, pw + 81920, 256, b2 + l * DIM, nullptr, 0, xs);        // x += ff2
        __syncthreads();
    }

    // ---------------- final LN (in place, fp32) ----------------------------
    for (int r = warp; r < MROWS; r += 8) {
        float* row = xs + r * DIM;
        float v[8], su = 0.f, su2 = 0.f;
        #pragma unroll
        for (int i = 0; i < 8; i++) { v[i] = row[lane + i * 32]; su += v[i]; su2 += v[i] * v[i]; }
        float2 rd = warp_red2(su, su2);
        float m = rd.x * (1.f / DIM), var = rd.y * (1.f / DIM) - m * m;
        float rs = rsqrtf(var + 1e-5f);
        #pragma unroll
        for (int i = 0; i < 8; i++) {
            int c = lane + i * 32;
            row[c] = (v[i] - m) * rs * flng[c] + flnb[c];
        }
    }
    __syncthreads();
    // mean over 4 tokens
    float* ms = (float*)(smem + QKV_OFF);  // [16][256] fp32
    for (int idx = tid; idx < TS * DIM; idx += 256) {
        int s = idx >> 8, c = idx & 255;
        const float* bp = xs + (s * 4) * DIM + c;
        ms[idx] = 0.25f * (bp[0] + bp[DIM] + bp[2 * DIM] + bp[3 * DIM]);
    }
    __syncthreads();
    // out LN -> global
    for (int r = warp; r < TS; r += 8) {
        const float* row = ms + r * DIM;
        float v[8], su = 0.f, su2 = 0.f;
        #pragma unroll
        for (int i = 0; i < 8; i++) { v[i] = row[lane + i * 32]; su += v[i]; su2 += v[i] * v[i]; }
        float2 rd = warp_red2(su, su2);
        float m = rd.x * (1.f / DIM), var = rd.y * (1.f / DIM) - m * m;
        float rs = rsqrtf(var + 1e-5f);
        #pragma unroll
        for (int i = 0; i < 8; i++) {
            int c = lane + i * 32;
            out[(size_t)(s0 + r) * DIM + c] = (v[i] - m) * rs * olng[c] + olnb[c];
        }
    }
}

extern "C" void kernel_launch(void* const* d_in, const int* in_sizes, int n_in,
                              void* d_out, int out_size) {
    const float* ge      = (const float*)d_in[0];
    const float* pe      = (const float*)d_in[1];
    const float* sfeat   = (const float*)d_in[2];
    const float* ppi     = (const float*)d_in[3];
    const float* symW    = (const float*)d_in[4];
    const float* symb    = (const float*)d_in[5];
    const float* symg    = (const float*)d_in[6];
    const float* symbeta = (const float*)d_in[7];
    const float* tte     = (const float*)d_in[8];
    const float* Wqkv    = (const float*)d_in[9];
    const float* bqkv    = (const float*)d_in[10];
    const float* Wo      = (const float*)d_in[11];
    const float* bo      = (const float*)d_in[12];
    const float* ln1g    = (const float*)d_in[13];
    const float* ln1b    = (const float*)d_in[14];
    const float* ln2g    = (const float*)d_in[15];
    const float* ln2b    = (const float*)d_in[16];
    const float* W1      = (const float*)d_in[17];
    const float* b1      = (const float*)d_in[18];
    const float* W2      = (const float*)d_in[19];
    const float* b2      = (const float*)d_in[20];
    const float* flng    = (const float*)d_in[21];
    const float* flnb    = (const float*)d_in[22];
    const float* olng    = (const float*)d_in[23];
    const float* olnb    = (const float*)d_in[24];

    int B = in_sizes[0] / DIM;

    cudaFuncSetAttribute(fused_kernel, cudaFuncAttributeMaxDynamicSharedMemorySize, SMEM_BYTES);

    pack_all<<<1152, 256>>>(Wqkv, Wo, W1, W2);

    fused_kernel<<<B / TS, 256, SMEM_BYTES>>>(
        ge, pe, sfeat, ppi, symW, symb, symg, symbeta, tte,
        bqkv, bo, ln1g, ln1b, ln2g, ln2b, b1, b2,
        flng, flnb, olng, olnb, (float*)d_out);
}

// round 10
// speedup vs baseline: 1.2027x; 1.0420x over previous
#include <cuda_runtime.h>
#include <cuda_bf16.h>
#include <math.h>

// ---------------------------------------------------------------------------
// CrossAttentionFusion: fully fused 3-layer transformer (seq=4) on GB300.
// R7 (= R6 design, compile-fixed): 4-wide n-groups (A loaded once per 256-col
// GEMM), weights repacked for LDG.128 (2 loads / kt), one-kt-ahead B prefetch.
// ---------------------------------------------------------------------------

#define TS 16          // samples per CTA
#define MROWS 64       // token rows per CTA (= TS*4)
#define DIM 256
#define HB_STRIDE 264  // bf16 elems, padded (528B rows: conflict-free ldmatrix)
#define QS 776         // qkv smem stride (768 + 8 pad) -> 1552B rows

#define XS_OFF   0
#define HB_OFF   65536
#define QKV_OFF  99328
#define SMEM_BYTES 198656

// Packed weights, per layer 98304 uint2:
// layout [group][kt][lane][nt] (group = 4 n-tiles = 32 cols; 2048 uint2/group)
// qkv: groups 0..23 (off 0), Wo: off 49152, W1: off 65536, W2: off 81920.
__device__ __align__(16) uint2 g_packed[3 * 98304];

// ---------------------------------------------------------------------------
// Pack ALL fp32 weights into grouped mma B-fragment order in ONE launch.
// Fragment (m16n8k16, .row.col): thread t holds b={B[k0][n],B[k0+1][n]},
//                                  {B[k0+8][n],B[k0+9][n]}
// with k0=kt*16+(t%4)*2, n=(group*4+nt)*8+(t/4).
// Linear index within a matrix: ((group*16 + kt)*32 + lane)*4 + nt.
// ---------------------------------------------------------------------------
__global__ void pack_all(const float* __restrict__ Wqkv, const float* __restrict__ Wo,
                         const float* __restrict__ W1, const float* __restrict__ W2) {
    int id = blockIdx.x * 256 + threadIdx.x;        // 0 .. 294911
    int l = id / 98304;
    int r = id - l * 98304;
    const float* src;
    int N, idx;
    if (r < 49152)      { src = Wqkv + (size_t)l * 196608; N = 768; idx = r; }
    else if (r < 65536) { src = Wo + (size_t)l * 65536; N = 256; idx = r - 49152; }
    else if (r < 81920) { src = W1 + (size_t)l * 65536; N = 256; idx = r - 65536; }
    else                { src = W2 + (size_t)l * 65536; N = 256; idx = r - 81920; }
    int group = idx >> 11;
    int rem = idx & 2047;
    int kt = rem >> 7;
    int lane = (rem >> 2) & 31;
    int nt = rem & 3;
    int g = lane >> 2, tg = lane & 3;
    int k0 = kt * 16 + tg * 2;
    int n = (group * 4 + nt) * 8 + g;
    unsigned lo0 = __bfloat16_as_ushort(__float2bfloat16(src[(size_t)k0 * N + n]));
    unsigned hi0 = __bfloat16_as_ushort(__float2bfloat16(src[(size_t)(k0 + 1) * N + n]));
    unsigned lo1 = __bfloat16_as_ushort(__float2bfloat16(src[(size_t)(k0 + 8) * N + n]));
    unsigned hi1 = __bfloat16_as_ushort(__float2bfloat16(src[(size_t)(k0 + 9) * N + n]));
    g_packed[id] = make_uint2(lo0 | (hi0 << 16), lo1 | (hi1 << 16));
}

__device__ __forceinline__ float gelu_exact(float v) {
    return 0.5f * v * (1.0f + erff(v * 0.70710678118654752f));
}

__device__ __forceinline__ float2 warp_red2(float s, float s2) {
    #pragma unroll
    for (int o = 16; o; o >>= 1) {
        s  += __shfl_xor_sync(0xffffffffu, s, o);
        s2 += __shfl_xor_sync(0xffffffffu, s2, o);
    }
    return make_float2(s, s2);
}

#define MMA_OP(AC, A0, A1, A2, A3, BX, BY)                                     \
    asm volatile(                                                              \
        "mma.sync.aligned.m16n8k16.row.col.f32.bf16.bf16.f32 "                 \
        "{%0,%1,%2,%3}, {%4,%5,%6,%7}, {%8,%9}, {%0,%1,%2,%3};\n"              \
        : "+f"(AC[0]), "+f"(AC[1]), "+f"(AC[2]), "+f"(AC[3])                   \
        : "r"(A0), "r"(A1), "r"(A2), "r"(A3), "r"(BX), "r"(BY))

// ---------------------------------------------------------------------------
// C[64, N] = A[64, 256]_bf16smem @ Wpacked + bias.
// Each warp owns one 32-col group per pass (disjoint across warps), walks all
// 4 m-tiles; A loaded via ldmatrix.x4 once per pass; B via 2x LDG.128 per kt
// with one-kt-ahead prefetch.
// MODE 0: store bf16 to out; MODE 1: store bf16 gelu(.); MODE 2: xs += .
// ---------------------------------------------------------------------------
template <int MODE>
__device__ __forceinline__ void gemm64(const __nv_bfloat16* __restrict__ A, int lda,
                                       const uint2* __restrict__ W, int N,
                                       const float* __restrict__ bias,
                                       __nv_bfloat16* __restrict__ out, int ostride,
                                       float* __restrict__ xs) {
    const int lane = threadIdx.x & 31, warp = threadIdx.x >> 5;
    const int g = lane >> 2, tg = lane & 3;
    const int arow = lane & 15;            // ldmatrix row within m-tile
    const int acol = (lane >> 4) << 3;     // ldmatrix col half-select
    unsigned sbase = (unsigned)__cvta_generic_to_shared(A);
    unsigned amt[4];
    #pragma unroll
    for (int mt = 0; mt < 4; mt++)
        amt[mt] = sbase + (unsigned)(((mt * 16 + arow) * lda + acol) * 2);

    const int npasses = N >> 8;
    for (int p = 0; p < npasses; p++) {
        const int grp = p * 8 + warp;
        float acc[4][4][4];  // [mt][nt][frag]
        #pragma unroll
        for (int mt = 0; mt < 4; mt++)
            #pragma unroll
            for (int nt = 0; nt < 4; nt++)
                acc[mt][nt][0] = acc[mt][nt][1] = acc[mt][nt][2] = acc[mt][nt][3] = 0.f;

        // uint4 view: element (grp,kt,lane,nt pair) at uint4 idx (grp*16+kt)*64 + lane*2
        const uint4* wp = (const uint4*)W + (size_t)grp * 1024 + lane * 2;
        uint4 b01 = wp[0], b23 = wp[1];
        #pragma unroll
        for (int kt = 0; kt < 16; kt++) {
            uint4 nb01, nb23;
            if (kt < 15) { nb01 = wp[(kt + 1) * 64]; nb23 = wp[(kt + 1) * 64 + 1]; }
            unsigned a[4][4];
            #pragma unroll
            for (int mt = 0; mt < 4; mt++) {
                unsigned aaddr = amt[mt] + (unsigned)(kt * 32);
                asm volatile(
                    "ldmatrix.sync.aligned.m8n8.x4.shared.b16 {%0,%1,%2,%3}, [%4];\n"
                    : "=r"(a[mt][0]), "=r"(a[mt][1]), "=r"(a[mt][2]), "=r"(a[mt][3])
                    : "r"(aaddr));
            }
            #pragma unroll
            for (int mt = 0; mt < 4; mt++) {
                MMA_OP(acc[mt][0], a[mt][0], a[mt][1], a[mt][2], a[mt][3], b01.x, b01.y);
                MMA_OP(acc[mt][1], a[mt][0], a[mt][1], a[mt][2], a[mt][3], b01.z, b01.w);
                MMA_OP(acc[mt][2], a[mt][0], a[mt][1], a[mt][2], a[mt][3], b23.x, b23.y);
                MMA_OP(acc[mt][3], a[mt][0], a[mt][1], a[mt][2], a[mt][3], b23.z, b23.w);
            }
            b01 = nb01; b23 = nb23;
        }
        // epilogue
        #pragma unroll
        for (int nt = 0; nt < 4; nt++) {
            const int cc = (grp * 4 + nt) * 8 + tg * 2;
            const float bb0 = bias[cc], bb1 = bias[cc + 1];
            #pragma unroll
            for (int mt = 0; mt < 4; mt++) {
                const int r0 = mt * 16 + g, r1 = r0 + 8;
                float v00 = acc[mt][nt][0] + bb0, v01 = acc[mt][nt][1] + bb1;
                float v10 = acc[mt][nt][2] + bb0, v11 = acc[mt][nt][3] + bb1;
                if (MODE == 2) {
                    xs[r0 * DIM + cc]     += v00;
                    xs[r0 * DIM + cc + 1] += v01;
                    xs[r1 * DIM + cc]     += v10;
                    xs[r1 * DIM + cc + 1] += v11;
                } else {
                    if (MODE == 1) {
                        v00 = gelu_exact(v00); v01 = gelu_exact(v01);
                        v10 = gelu_exact(v10); v11 = gelu_exact(v11);
                    }
                    *(__nv_bfloat162*)(out + r0 * ostride + cc) = __floats2bfloat162_rn(v00, v01);
                    *(__nv_bfloat162*)(out + r1 * ostride + cc) = __floats2bfloat162_rn(v10, v11);
                }
            }
        }
    }
}

// LN all 64 rows of xs -> bf16 dst (gamma/beta per col)
__device__ __forceinline__ void ln64_bf16(const float* __restrict__ xs,
                                          const float* __restrict__ gm,
                                          const float* __restrict__ bt,
                                          __nv_bfloat16* __restrict__ dst, int ds) {
    const int lane = threadIdx.x & 31, warp = threadIdx.x >> 5;
    for (int r = warp; r < MROWS; r += 8) {
        const float* row = xs + r * DIM;
        float v[8], s = 0.f, s2 = 0.f;
        #pragma unroll
        for (int i = 0; i < 8; i++) { v[i] = row[lane + i * 32]; s += v[i]; s2 += v[i] * v[i]; }
        float2 rd = warp_red2(s, s2);
        float m = rd.x * (1.f / DIM);
        float var = rd.y * (1.f / DIM) - m * m;
        float rs = rsqrtf(var + 1e-5f);
        #pragma unroll
        for (int i = 0; i < 8; i++) {
            int c = lane + i * 32;
            dst[r * ds + c] = __float2bfloat16((v[i] - m) * rs * gm[c] + bt[c]);
        }
    }
}

__global__ void __launch_bounds__(256, 1) fused_kernel(
    const float* __restrict__ ge, const float* __restrict__ pe,
    const float* __restrict__ sfeat, const float* __restrict__ ppi,
    const float* __restrict__ symW, const float* __restrict__ symb,
    const float* __restrict__ symg, const float* __restrict__ symbeta,
    const float* __restrict__ tte,
    const float* __restrict__ bqkv, const float* __restrict__ bo,
    const float* __restrict__ ln1g, const float* __restrict__ ln1b,
    const float* __restrict__ ln2g, const float* __restrict__ ln2b,
    const float* __restrict__ b1, const float* __restrict__ b2,
    const float* __restrict__ flng, const float* __restrict__ flnb,
    const float* __restrict__ olng, const float* __restrict__ olnb,
    float* __restrict__ out) {
    extern __shared__ char smem[];
    float* xs = (float*)(smem + XS_OFF);                       // [64][256] fp32 residual
    __nv_bfloat16* hb = (__nv_bfloat16*)(smem + HB_OFF);       // [64][264] bf16 scratch A
    __nv_bfloat16* qkvb = (__nv_bfloat16*)(smem + QKV_OFF);    // [64][776] bf16 qkv / ff1
    const int tid = threadIdx.x;
    const int lane = tid & 31, warp = tid >> 5;
    const int s0 = blockIdx.x * TS;

    // ---------------- Phase 0: build x = stack(tokens) + tte -------------
    float* sfs = (float*)(smem + QKV_OFF);  // [16][64] sym_feat staging
    for (int idx = tid; idx < TS * 64; idx += 256) {
        int s = idx >> 6, j = idx & 63;
        sfs[idx] = sfeat[(size_t)(s0 + s) * 64 + j];
    }
    for (int idx = tid; idx < TS * DIM; idx += 256) {
        int s = idx >> 8, c = idx & 255;
        size_t gsrc = (size_t)(s0 + s) * DIM + c;
        xs[(s * 4 + 0) * DIM + c] = ge[gsrc];
        xs[(s * 4 + 1) * DIM + c] = pe[gsrc];
        xs[(s * 4 + 3) * DIM + c] = ppi[gsrc];
    }
    __syncthreads();
    {   // sym projection: thread = output column
        int c = tid;
        float acc[TS];
        #pragma unroll
        for (int s = 0; s < TS; s++) acc[s] = 0.f;
        for (int j = 0; j < 64; j++) {
            float w = symW[(size_t)j * DIM + c];
            #pragma unroll
            for (int s = 0; s < TS; s++) acc[s] += sfs[s * 64 + j] * w;
        }
        float bb = symb[c];
        #pragma unroll
        for (int s = 0; s < TS; s++) xs[(s * 4 + 2) * DIM + c] = acc[s] + bb;
    }
    __syncthreads();
    // sym LN in place on rows 4s+2
    for (int s = warp; s < TS; s += 8) {
        float* row = xs + (s * 4 + 2) * DIM;
        float v[8], su = 0.f, su2 = 0.f;
        #pragma unroll
        for (int i = 0; i < 8; i++) { v[i] = row[lane + i * 32]; su += v[i]; su2 += v[i] * v[i]; }
        float2 rd = warp_red2(su, su2);
        float m = rd.x * (1.f / DIM), var = rd.y * (1.f / DIM) - m * m;
        float rs = rsqrtf(var + 1e-5f);
        #pragma unroll
        for (int i = 0; i < 8; i++) {
            int c = lane + i * 32;
            row[c] = (v[i] - m) * rs * symg[c] + symbeta[c];
        }
    }
    __syncthreads();
    for (int idx = tid; idx < MROWS * DIM; idx += 256) {
        int r = idx >> 8, c = idx & 255;
        xs[idx] += tte[(r & 3) * DIM + c];
    }
    __syncthreads();

    // ---------------- 3 transformer layers --------------------------------
    for (int l = 0; l < 3; l++) {
        const uint2* pw = g_packed + (size_t)l * 98304;
        ln64_bf16(xs, ln1g + l * DIM, ln1b + l * DIM, hb, HB_STRIDE);
        __syncthreads();
        gemm64<0>(hb, HB_STRIDE, pw, 768, bqkv + l * 768, qkvb, QS, xs);
        __syncthreads();
        // attention: thread = (sample, head); writes o into hb
        if (tid < 128) {
            const int s = tid >> 3, h = tid & 7;
            const __nv_bfloat16* qb = qkvb + (s * 4) * QS + h * 32;
            const __nv_bfloat16* kb = qb + 256;
            const __nv_bfloat16* vb = qb + 512;
            float S[4][4];
            #pragma unroll
            for (int i = 0; i < 4; i++)
                #pragma unroll
                for (int j = 0; j < 4; j++) S[i][j] = 0.f;
            for (int d2 = 0; d2 < 16; d2++) {
                float2 qv[4], kv[4];
                #pragma unroll
                for (int i = 0; i < 4; i++) {
                    qv[i] = __bfloat1622float2(*(const __nv_bfloat162*)(qb + i * QS + d2 * 2));
                    kv[i] = __bfloat1622float2(*(const __nv_bfloat162*)(kb + i * QS + d2 * 2));
                }
                #pragma unroll
                for (int i = 0; i < 4; i++)
                    #pragma unroll
                    for (int j = 0; j < 4; j++)
                        S[i][j] += qv[i].x * kv[j].x + qv[i].y * kv[j].y;
            }
            const float scale = 0.17677669529663687f;  // 1/sqrt(32)
            #pragma unroll
            for (int i = 0; i < 4; i++) {
                float mx = -1e30f;
                #pragma unroll
                for (int j = 0; j < 4; j++) { S[i][j] *= scale; mx = fmaxf(mx, S[i][j]); }
                float sm = 0.f;
                #pragma unroll
                for (int j = 0; j < 4; j++) { S[i][j] = expf(S[i][j] - mx); sm += S[i][j]; }
                float inv = 1.f / sm;
                #pragma unroll
                for (int j = 0; j < 4; j++) S[i][j] *= inv;
            }
            for (int d2 = 0; d2 < 16; d2++) {
                float2 vv[4];
                #pragma unroll
                for (int j = 0; j < 4; j++)
                    vv[j] = __bfloat1622float2(*(const __nv_bfloat162*)(vb + j * QS + d2 * 2));
                #pragma unroll
                for (int i = 0; i < 4; i++) {
                    float ox = 0.f, oy = 0.f;
                    #pragma unroll
                    for (int j = 0; j < 4; j++) { ox += S[i][j] * vv[j].x; oy += S[i][j] * vv[j].y; }
                    *(__nv_bfloat162*)(hb + (s * 4 + i) * HB_STRIDE + h * 32 + d2 * 2) =
                        __floats2bfloat162_rn(ox, oy);
                }
            }
        }
        __syncthreads();
        gemm64<2>(hb, HB_STRIDE, pw + 49152, 256, bo + l * DIM, nullptr, 0, xs);   // x += o @ Wo
        __syncthreads();
        ln64_bf16(xs, ln2g + l * DIM, ln2b + l * DIM, hb, HB_STRIDE);
        __syncthreads();
        gemm64<1>(hb, HB_STRIDE, pw + 65536, 256, b1 + l * DIM, qkvb, QS, xs);     // ff1 = gelu
        __syncthreads();
        gemm64<2>(qkvb, QS, pw + 81920, 256, b2 + l * DIM, nullptr, 0, xs);        // x += ff2
        __syncthreads();
    }

    // ---------------- final LN (in place, fp32) ----------------------------
    for (int r = warp; r < MROWS; r += 8) {
        float* row = xs + r * DIM;
        float v[8], su = 0.f, su2 = 0.f;
        #pragma unroll
        for (int i = 0; i < 8; i++) { v[i] = row[lane + i * 32]; su += v[i]; su2 += v[i] * v[i]; }
        float2 rd = warp_red2(su, su2);
        float m = rd.x * (1.f / DIM), var = rd.y * (1.f / DIM) - m * m;
        float rs = rsqrtf(var + 1e-5f);
        #pragma unroll
        for (int i = 0; i < 8; i++) {
            int c = lane + i * 32;
            row[c] = (v[i] - m) * rs * flng[c] + flnb[c];
        }
    }
    __syncthreads();
    // mean over 4 tokens
    float* ms = (float*)(smem + QKV_OFF);  // [16][256] fp32
    for (int idx = tid; idx < TS * DIM; idx += 256) {
        int s = idx >> 8, c = idx & 255;
        const float* bp = xs + (s * 4) * DIM + c;
        ms[idx] = 0.25f * (bp[0] + bp[DIM] + bp[2 * DIM] + bp[3 * DIM]);
    }
    __syncthreads();
    // out LN -> global
    for (int r = warp; r < TS; r += 8) {
        const float* row = ms + r * DIM;
        float v[8], su = 0.f, su2 = 0.f;
        #pragma unroll
        for (int i = 0; i < 8; i++) { v[i] = row[lane + i * 32]; su += v[i]; su2 += v[i] * v[i]; }
        float2 rd = warp_red2(su, su2);
        float m = rd.x * (1.f / DIM), var = rd.y * (1.f / DIM) - m * m;
        float rs = rsqrtf(var + 1e-5f);
        #pragma unroll
        for (int i = 0; i < 8; i++) {
            int c = lane + i * 32;
            out[(size_t)(s0 + r) * DIM + c] = (v[i] - m) * rs * olng[c] + olnb[c];
        }
    }
}

extern "C" void kernel_launch(void* const* d_in, const int* in_sizes, int n_in,
                              void* d_out, int out_size) {
    const float* ge      = (const float*)d_in[0];
    const float* pe      = (const float*)d_in[1];
    const float* sfeat   = (const float*)d_in[2];
    const float* ppi     = (const float*)d_in[3];
    const float* symW    = (const float*)d_in[4];
    const float* symb    = (const float*)d_in[5];
    const float* symg    = (const float*)d_in[6];
    const float* symbeta = (const float*)d_in[7];
    const float* tte     = (const float*)d_in[8];
    const float* Wqkv    = (const float*)d_in[9];
    const float* bqkv    = (const float*)d_in[10];
    const float* Wo      = (const float*)d_in[11];
    const float* bo      = (const float*)d_in[12];
    const float* ln1g    = (const float*)d_in[13];
    const float* ln1b    = (const float*)d_in[14];
    const float* ln2g    = (const float*)d_in[15];
    const float* ln2b    = (const float*)d_in[16];
    const float* W1      = (const float*)d_in[17];
    const float* b1      = (const float*)d_in[18];
    const float* W2      = (const float*)d_in[19];
    const float* b2      = (const float*)d_in[20];
    const float* flng    = (const float*)d_in[21];
    const float* flnb    = (const float*)d_in[22];
    const float* olng    = (const float*)d_in[23];
    const float* olnb    = (const float*)d_in[24];

    int B = in_sizes[0] / DIM;

    cudaFuncSetAttribute(fused_kernel, cudaFuncAttributeMaxDynamicSharedMemorySize, SMEM_BYTES);

    pack_all<<<1152, 256>>>(Wqkv, Wo, W1, W2);

    fused_kernel<<<B / TS, 256, SMEM_BYTES>>>(
        ge, pe, sfeat, ppi, symW, symb, symg, symbeta, tte,
        bqkv, bo, ln1g, ln1b, ln2g, ln2b, b1, b2,
        flng, flnb, olng, olnb, (float*)d_out);
}